// round 6
// baseline (speedup 1.0000x reference)
#include <cuda_runtime.h>
#include <cuda_fp16.h>

// Problem shape (fixed by the dataset)
#define BATCH 8
#define CHAN  3
#define HH    720
#define WW    1280
#define HW    (HH * WW)
#define NROWS (BATCH * HH)
#define EPSV  1e-6f
#define K_LOG2 0.49978218f     // log2(1.414)

// flow_y == 0 -> 1-D splat within the row: pixel x contributes to bins
// x0 = floor(x - d) (weight wa) and x0+1 (weight wc), d in [0,20].
// Accumulate (c0,c1) and (c2,wsum) as two __half2 shared planes with f16x2
// shared atomics: 4 ATOMS per pixel (hard floor for 8 half payloads on
// 32-bit shared atomics).
//
// R4/R5 showed global REDs cost the same l1tex wavefronts as shared ATOMS
// plus scratch traffic -> all-shared is optimal. This round removes the
// per-pixel bounds branches via guard bands so both atomics are
// unconditional, trimming ALU/branch pressure on the 46%-issue hot loop.
//
// Guard bands: slots [-32, WW+32). x0 >= x-21 >= -21, x1 <= x+1 <= WW.
#define GUARD 32
#define PLANE (WW + 2 * GUARD)   // 1344 slots

__global__ __launch_bounds__(320) void splat_kernel(
    const float* __restrict__ im,
    const float* __restrict__ disp,
    float* __restrict__ out)
{
    __shared__ __half2 sA_raw[PLANE];   // (c0, c1), slots [-32, WW+32)
    __shared__ __half2 sB_raw[PLANE];   // (c2, w )
    __half2* sA = sA_raw + GUARD;
    __half2* sB = sB_raw + GUARD;

    const int row = blockIdx.x;      // b*HH + y
    const int b   = row / HH;
    const int y   = row - b * HH;
    const int tid = threadIdx.x;

    // ---- zero both planes: 2*1344 half2 = 672 uint4 ----
    {
        uint4 z = make_uint4(0u, 0u, 0u, 0u);
        ((uint4*)sA_raw)[tid] = z;                 // 320
        ((uint4*)sB_raw)[tid] = z;                 // 320
        if (tid < 16) {
            ((uint4*)sA_raw)[320 + tid] = z;       // 16
            ((uint4*)sB_raw)[320 + tid] = z;       // 16
        }
    }
    __syncthreads();

    // ---- splat phase: 4 consecutive pixels per thread ----
    const float4* d_row4 = (const float4*)(disp + (size_t)row * WW);
    const float*  im_row = im  + (size_t)b * CHAN * HW + (size_t)y * WW;
    float*        o_row  = out + (size_t)b * CHAN * HW + (size_t)y * WW;

    const int xb = tid * 4;
    float4 d4 = d_row4[tid];
    float4 c0 = ((const float4*)(im_row))[tid];
    float4 c1 = ((const float4*)(im_row + HW))[tid];
    float4 c2 = ((const float4*)(im_row + 2 * HW))[tid];

    const float dd[4] = {d4.x, d4.y, d4.z, d4.w};
    const float p0[4] = {c0.x, c0.y, c0.z, c0.w};
    const float p1[4] = {c1.x, c1.y, c1.z, c1.w};
    const float p2[4] = {c2.x, c2.y, c2.z, c2.w};

    #pragma unroll
    for (int k = 0; k < 4; k++) {
        float d = dd[k];
        float w;
        asm("ex2.approx.f32 %0, %1;" : "=f"(w) : "f"(d * K_LOG2));
        float tx  = (float)(xb + k) - d;
        int   x0  = __float2int_rd(tx);
        float fc  = tx - (float)x0;   // weight toward x0+1
        float wc  = w * fc;           // combined weight at x0+1
        float wa  = w - wc;           // combined weight at x0

        float v0 = p0[k], v1 = p1[k], v2 = p2[k];

        // unconditional: guard bands absorb x0 in [-21,-1] and x1 == WW
        atomicAdd(&sA[x0],     __floats2half2_rn(v0 * wa, v1 * wa));
        atomicAdd(&sB[x0],     __floats2half2_rn(v2 * wa, wa));
        atomicAdd(&sA[x0 + 1], __floats2half2_rn(v0 * wc, v1 * wc));
        atomicAdd(&sB[x0 + 1], __floats2half2_rn(v2 * wc, wc));
    }
    __syncthreads();

    // ---- normalize phase: uint4 reads from shared, float4 writes ----
    uint4 ua = ((const uint4*)sA)[tid];   // 4 pixels of (c0,c1)
    uint4 ub = ((const uint4*)sB)[tid];   // 4 pixels of (c2,w)
    const unsigned va[4] = {ua.x, ua.y, ua.z, ua.w};
    const unsigned vb[4] = {ub.x, ub.y, ub.z, ub.w};

    float4 r0, r1, r2;
    float* r0p = &r0.x; float* r1p = &r1.x; float* r2p = &r2.x;
    #pragma unroll
    for (int j = 0; j < 4; j++) {
        __half2 a  = *(const __half2*)&va[j];
        __half2 bb = *(const __half2*)&vb[j];
        float n0 = __low2float(a),  n1 = __high2float(a);
        float n2 = __low2float(bb), ws = __high2float(bb);
        float inv;
        asm("rcp.approx.f32 %0, %1;" : "=f"(inv) : "f"(fmaxf(ws, EPSV)));
        r0p[j] = n0 * inv;
        r1p[j] = n1 * inv;
        r2p[j] = n2 * inv;
    }
    ((float4*)o_row)[tid]            = r0;
    ((float4*)(o_row + HW))[tid]     = r1;
    ((float4*)(o_row + 2 * HW))[tid] = r2;
}

extern "C" void kernel_launch(void* const* d_in, const int* in_sizes, int n_in,
                              void* d_out, int out_size) {
    const float* im   = (const float*)d_in[0];   // [8,3,720,1280] fp32
    const float* disp = (const float*)d_in[1];   // [8,1,720,1280] fp32
    float* out = (float*)d_out;                  // [8,3,720,1280] fp32

    splat_kernel<<<NROWS, 320>>>(im, disp, out);
}